// round 6
// baseline (speedup 1.0000x reference)
#include <cuda_runtime.h>
#include <cstddef>

#define BB 2048
#define TT 1024
#define DD 64
#define HH 32

typedef unsigned long long u64;

// ---- packed fp32x2 helpers (sm_100+) ----
__device__ __forceinline__ u64 ffma2(u64 a, u64 b, u64 c) {
    u64 d;
    asm("fma.rn.f32x2 %0, %1, %2, %3;" : "=l"(d) : "l"(a), "l"(b), "l"(c));
    return d;
}
__device__ __forceinline__ u64 pack2(float lo, float hi) {
    u64 r;
    asm("mov.b64 %0, {%1, %2};" : "=l"(r) : "f"(lo), "f"(hi));
    return r;
}
__device__ __forceinline__ float sum2(u64 v) {
    float a, b;
    asm("mov.b64 {%0, %1}, %2;" : "=f"(a), "=f"(b) : "l"(v));
    return a + b;
}
__device__ __forceinline__ float fast_sigmoid(float x) {
    float e;
    asm("ex2.approx.f32 %0, %1;" : "=f"(e) : "f"(-1.4426950408889634f * x));
    float r;
    asm("rcp.approx.f32 %0, %1;" : "=f"(r) : "f"(1.0f + e));
    return r;
}
__device__ __forceinline__ float fast_tanh(float x) {
    return fmaf(2.0f, fast_sigmoid(2.0f * x), -1.0f);
}

// Named barriers: A(id=1) producers arrive / consumers sync (hh1(t), gx(t+1) ready)
//                 B(id=2) consumers arrive / producers sync (h1(t) published)
#define BAR_SYNC_A()   asm volatile("bar.sync 1, 256;"   ::: "memory")
#define BAR_ARRIVE_A() asm volatile("bar.arrive 1, 256;" ::: "memory")
#define BAR_SYNC_B()   asm volatile("bar.sync 2, 256;"   ::: "memory")
#define BAR_ARRIVE_B() asm volatile("bar.arrive 2, 256;" ::: "memory")

// layer-0 input gemm, half-K (32), 8 rows, register weights
__device__ __forceinline__ void gx_gemm(const u64* __restrict__ pwr,
                                        const u64* __restrict__ pwz,
                                        const u64* __restrict__ pwn,
                                        const float4* __restrict__ xsw,
                                        float* __restrict__ gout,
                                        int lane, float b_r, float b_z, float b_n) {
    u64 ar[8], az[8], an[8];
#pragma unroll
    for (int r = 0; r < 8; r++) {
        ar[r] = pack2(b_r, 0.f); az[r] = pack2(b_z, 0.f); an[r] = pack2(b_n, 0.f);
    }
#pragma unroll
    for (int kk = 0; kk < 8; kk++) {
#pragma unroll
        for (int r = 0; r < 8; r++) {
            ulonglong2 xv = *(const ulonglong2*)(xsw + r * 8 + kk);
            ar[r] = ffma2(pwr[2 * kk], xv.x, ar[r]); ar[r] = ffma2(pwr[2 * kk + 1], xv.y, ar[r]);
            az[r] = ffma2(pwz[2 * kk], xv.x, az[r]); az[r] = ffma2(pwz[2 * kk + 1], xv.y, az[r]);
            an[r] = ffma2(pwn[2 * kk], xv.x, an[r]); an[r] = ffma2(pwn[2 * kk + 1], xv.y, an[r]);
        }
    }
#pragma unroll
    for (int r = 0; r < 8; r++) {
        gout[r * 96 + lane]      = sum2(ar[r]);
        gout[r * 96 + 32 + lane] = sum2(az[r]);
        gout[r * 96 + 64 + lane] = sum2(an[r]);
    }
}

__global__ void __launch_bounds__(256, 1)
gru2_kernel(const float* __restrict__ x,
            const float* __restrict__ wih0, const float* __restrict__ whh0,
            const float* __restrict__ bih0, const float* __restrict__ bhh0,
            const float* __restrict__ wih1, const float* __restrict__ whh1,
            const float* __restrict__ bih1, const float* __restrict__ bhh1,
            const float* __restrict__ wcls, const float* __restrict__ bcls,
            float* __restrict__ out)
{
    extern __shared__ float4 sm4[];
    float4* w4ih1 = sm4;                     // [8][96] f4 = 12KB
    float4* w4hh1 = sm4 + 768;               // 12KB
    float*  gxs   = (float*)(sm4 + 1536);    // [2 slot][2 half][16 row][96] = 24KB
    float*  hh1b  = gxs + 6144;              // [16 row][96] = 6KB
    float*  h1s   = hh1b + 1536;             // [2 slot][16 row][32] = 4KB
    float*  h0s   = h1s + 1024;              // [16 row][32] = 2KB
    float4* xs    = (float4*)(h0s + 512);    // [4 pwarp][8 row][8] f4 = 4KB

    const int tid  = threadIdx.x;
    const int warp = tid >> 5;
    const int lane = tid & 31;
    const int rowbase16 = blockIdx.x * 16;

    // cooperative transpose of layer-1 weights: [kk][gate] float4
    for (int idx = tid; idx < 768; idx += 256) {
        int g = idx % 96, kk = idx / 96;
        w4ih1[kk * 96 + g] = *(const float4*)(wih1 + g * 32 + kk * 4);
        w4hh1[kk * 96 + g] = *(const float4*)(whh1 + g * 32 + kk * 4);
    }
    // zero h1s (both slots) + h0s (contiguous 1536 floats)
    for (int i = tid; i < 1536; i += 256) h1s[i] = 0.f;

    // ---------------- per-role registers + producer prologue ----------------
    u64 rw0[16], rw1[16], rw2[16];           // role-dependent register weights
    float bA = 0.f, bZ = 0.f, bN = 0.f;      // role-dependent biases
    float br1i = 0.f, bz1i = 0.f, bn1i = 0.f, wc = 0.f, bc = 0.f;
    const float4 *xg0 = nullptr, *xg1 = nullptr;
    float4 *xst0 = nullptr, *xst1 = nullptr;
    float4 xb0, xb1;
    const float4* xsw = nullptr;

    if (warp < 4) {
        // consumer: W_hh0 register-resident (lane j holds gate rows j, 32+j, 64+j)
#pragma unroll
        for (int i = 0; i < 8; i++) {
            ulonglong2 a = *(const ulonglong2*)(whh0 + lane * 32 + i * 4);
            ulonglong2 b = *(const ulonglong2*)(whh0 + (32 + lane) * 32 + i * 4);
            ulonglong2 c = *(const ulonglong2*)(whh0 + (64 + lane) * 32 + i * 4);
            rw0[2 * i] = a.x; rw0[2 * i + 1] = a.y;
            rw1[2 * i] = b.x; rw1[2 * i + 1] = b.y;
            rw2[2 * i] = c.x; rw2[2 * i + 1] = c.y;
        }
        bA = bhh0[lane]; bZ = bhh0[32 + lane]; bN = bhh0[64 + lane];
        br1i = bih1[lane]; bz1i = bih1[32 + lane]; bn1i = bih1[64 + lane];
        wc = wcls[lane]; bc = bcls[0];
    } else {
        // producer: W_ih0 half-K register-resident
        const int p  = warp - 4;
        const int rg = (p & 1) * 8;
        const int kh = p >> 1;
#pragma unroll
        for (int i = 0; i < 8; i++) {
            ulonglong2 a = *(const ulonglong2*)(wih0 + lane * 64        + kh * 32 + i * 4);
            ulonglong2 b = *(const ulonglong2*)(wih0 + (32 + lane) * 64 + kh * 32 + i * 4);
            ulonglong2 c = *(const ulonglong2*)(wih0 + (64 + lane) * 64 + kh * 32 + i * 4);
            rw0[2 * i] = a.x; rw0[2 * i + 1] = a.y;
            rw1[2 * i] = b.x; rw1[2 * i + 1] = b.y;
            rw2[2 * i] = c.x; rw2[2 * i + 1] = c.y;
        }
        if (kh == 0) { bA = bih0[lane]; bZ = bih0[32 + lane]; bN = bih0[64 + lane]; }

        float4* xsww = xs + p * 64;
        xsw = xsww;
        const int s0 = lane, s1 = lane + 32;
        xg0  = (const float4*)(x + (size_t)(rowbase16 + rg + (s0 >> 3)) * TT * DD + kh * 32) + (s0 & 7);
        xg1  = (const float4*)(x + (size_t)(rowbase16 + rg + (s1 >> 3)) * TT * DD + kh * 32) + (s1 & 7);
        xst0 = xsww + s0;
        xst1 = xsww + s1;

        // prologue: gx(0) into slot 0
        xb0 = *xg0; xb1 = *xg1; xg0 += 16; xg1 += 16;
        *xst0 = xb0; *xst1 = xb1;
        __syncwarp();
        xb0 = *xg0; xb1 = *xg1; xg0 += 16; xg1 += 16;   // prefetch x(1)
        gx_gemm(rw0, rw1, rw2, xsw, gxs + kh * 1536 + rg * 96, lane, bA, bZ, bN);
    }

    __syncthreads();   // converged: gx(0), zeros, shared weights all visible

    if (warp < 4) {
        // ================= consumer =================
        float h0r[4] = {0.f, 0.f, 0.f, 0.f};
        float h1r[4] = {0.f, 0.f, 0.f, 0.f};
        const int rb = warp * 4;
        float* h0w = h0s + rb * 32;

        BAR_ARRIVE_B();   // h1(-1)=0 published

        for (int t = 0; t < TT; t++) {
            const float* g0 = gxs + (t & 1) * 3072 + rb * 96;
            const float* g1 = g0 + 1536;

            // ---- layer 0: hidden gemm (reg weights, reads old h0 in shared) ----
            u64 gr[4], gz[4], gn[4];
#pragma unroll
            for (int r = 0; r < 4; r++) {
                gr[r] = pack2(bA, 0.f); gz[r] = pack2(bZ, 0.f); gn[r] = pack2(bN, 0.f);
            }
#pragma unroll
            for (int kk = 0; kk < 8; kk++) {
#pragma unroll
                for (int r = 0; r < 4; r++) {
                    ulonglong2 hv = *(const ulonglong2*)(h0w + r * 32 + kk * 4);
                    gr[r] = ffma2(rw0[2 * kk], hv.x, gr[r]); gr[r] = ffma2(rw0[2 * kk + 1], hv.y, gr[r]);
                    gz[r] = ffma2(rw1[2 * kk], hv.x, gz[r]); gz[r] = ffma2(rw1[2 * kk + 1], hv.y, gz[r]);
                    gn[r] = ffma2(rw2[2 * kk], hv.x, gn[r]); gn[r] = ffma2(rw2[2 * kk + 1], hv.y, gn[r]);
                }
            }
#pragma unroll
            for (int r = 0; r < 4; r++) {
                float xr = g0[r * 96 + lane]      + g1[r * 96 + lane];
                float xz = g0[r * 96 + 32 + lane] + g1[r * 96 + 32 + lane];
                float xn = g0[r * 96 + 64 + lane] + g1[r * 96 + 64 + lane];
                float rg = fast_sigmoid(xr + sum2(gr[r]));
                float zg = fast_sigmoid(xz + sum2(gz[r]));
                float ng = fast_tanh(xn + rg * sum2(gn[r]));   // b_hh_n inside r* (torch GRU)
                h0r[r] = ng + zg * (h0r[r] - ng);
            }
            __syncwarp();
#pragma unroll
            for (int r = 0; r < 4; r++) h0w[r * 32 + lane] = h0r[r];
            __syncwarp();

            // ---- layer 1: input gemm (smem W_ih1, reads new h0) ----
            u64 cr[4], cz[4], cn[4];
#pragma unroll
            for (int r = 0; r < 4; r++) {
                cr[r] = pack2(br1i, 0.f); cz[r] = pack2(bz1i, 0.f); cn[r] = pack2(bn1i, 0.f);
            }
#pragma unroll
            for (int kk = 0; kk < 8; kk++) {
                ulonglong2 ir  = *(const ulonglong2*)(w4ih1 + kk * 96 + lane);
                ulonglong2 iz  = *(const ulonglong2*)(w4ih1 + kk * 96 + 32 + lane);
                ulonglong2 in_ = *(const ulonglong2*)(w4ih1 + kk * 96 + 64 + lane);
#pragma unroll
                for (int r = 0; r < 4; r++) {
                    ulonglong2 hv = *(const ulonglong2*)(h0w + r * 32 + kk * 4);
                    cr[r] = ffma2(ir.x,  hv.x, cr[r]); cr[r] = ffma2(ir.y,  hv.y, cr[r]);
                    cz[r] = ffma2(iz.x,  hv.x, cz[r]); cz[r] = ffma2(iz.y,  hv.y, cz[r]);
                    cn[r] = ffma2(in_.x, hv.x, cn[r]); cn[r] = ffma2(in_.y, hv.y, cn[r]);
                }
            }

            BAR_SYNC_A();   // hh1(t) (and gx(t+1)) now published by producers

            float* h1w = h1s + (t & 1) * 512 + rb * 32;
#pragma unroll
            for (int r = 0; r < 4; r++) {
                const float* s = hh1b + (rb + r) * 96;
                float rg = fast_sigmoid(sum2(cr[r]) + s[lane]);
                float zg = fast_sigmoid(sum2(cz[r]) + s[32 + lane]);
                float ng = fast_tanh(sum2(cn[r]) + rg * s[64 + lane]);
                h1r[r] = ng + zg * (h1r[r] - ng);
                h1w[r * 32 + lane] = h1r[r];
            }
            if (t + 1 < TT) BAR_ARRIVE_B();   // publish h1(t); last phase has no waiter
        }

        // ---- outputs: y [B], hidden [2,B,H] ----
#pragma unroll
        for (int r = 0; r < 4; r++) {
            int row = rowbase16 + rb + r;
            out[BB + row * HH + lane] = h0r[r];
            out[BB + BB * HH + row * HH + lane] = h1r[r];
            float p = h1r[r] * wc;
#pragma unroll
            for (int off = 16; off; off >>= 1) p += __shfl_xor_sync(0xffffffffu, p, off);
            if (lane == 0) out[row] = fast_sigmoid(p + bc);
        }
    } else {
        // ================= producer =================
        const int p  = warp - 4;
        const int rg = (p & 1) * 8;
        const int kh = p >> 1;
        const float bh_r = bhh1[lane], bh_z = bhh1[32 + lane], bh_n = bhh1[64 + lane];

        for (int t = 0; t < TT; t++) {
            BAR_SYNC_B();   // h1(t-1) published; gx slot (t+1)&1 free

            // ---- W_hh1 · h1(t-1) + b_hh1 for rows 4p..4p+3 (smem weights) ----
            const float* h1src = h1s + (((t + 1) & 1) * 512) + (p * 4) * 32;  // slot (t-1)&1
            u64 dr[4], dz[4], dn[4];
#pragma unroll
            for (int r = 0; r < 4; r++) {
                dr[r] = pack2(bh_r, 0.f); dz[r] = pack2(bh_z, 0.f); dn[r] = pack2(bh_n, 0.f);
            }
#pragma unroll
            for (int kk = 0; kk < 8; kk++) {
                ulonglong2 hr = *(const ulonglong2*)(w4hh1 + kk * 96 + lane);
                ulonglong2 hz = *(const ulonglong2*)(w4hh1 + kk * 96 + 32 + lane);
                ulonglong2 hn = *(const ulonglong2*)(w4hh1 + kk * 96 + 64 + lane);
#pragma unroll
                for (int r = 0; r < 4; r++) {
                    ulonglong2 hv = *(const ulonglong2*)(h1src + r * 32 + kk * 4);
                    dr[r] = ffma2(hr.x, hv.x, dr[r]); dr[r] = ffma2(hr.y, hv.y, dr[r]);
                    dz[r] = ffma2(hz.x, hv.x, dz[r]); dz[r] = ffma2(hz.y, hv.y, dz[r]);
                    dn[r] = ffma2(hn.x, hv.x, dn[r]); dn[r] = ffma2(hn.y, hv.y, dn[r]);
                }
            }
#pragma unroll
            for (int r = 0; r < 4; r++) {
                float* o = hh1b + (p * 4 + r) * 96;
                o[lane]      = sum2(dr[r]);
                o[32 + lane] = sum2(dz[r]);
                o[64 + lane] = sum2(dn[r]);
            }

            // ---- gx(t+1) (register W_ih0 half-K, 8 rows) ----
            if (t + 1 < TT) {
                *xst0 = xb0; *xst1 = xb1;
                __syncwarp();
                if (t + 2 < TT) { xb0 = *xg0; xb1 = *xg1; xg0 += 16; xg1 += 16; }
                gx_gemm(rw0, rw1, rw2, xsw,
                        gxs + ((t + 1) & 1) * 3072 + kh * 1536 + rg * 96,
                        lane, bA, bZ, bN);
            }
            BAR_ARRIVE_A();   // publish hh1(t) + gx(t+1)
        }
    }
}

extern "C" void kernel_launch(void* const* d_in, const int* in_sizes, int n_in,
                              void* d_out, int out_size) {
    (void)in_sizes; (void)n_in; (void)out_size;
    const float* x    = (const float*)d_in[0];
    const float* wih0 = (const float*)d_in[1];
    const float* whh0 = (const float*)d_in[2];
    const float* bih0 = (const float*)d_in[3];
    const float* bhh0 = (const float*)d_in[4];
    const float* wih1 = (const float*)d_in[5];
    const float* whh1 = (const float*)d_in[6];
    const float* bih1 = (const float*)d_in[7];
    const float* bhh1 = (const float*)d_in[8];
    const float* wcls = (const float*)d_in[9];
    const float* bcls = (const float*)d_in[10];
    float* out = (float*)d_out;

    const int smem_bytes = 65536;
    cudaFuncSetAttribute(gru2_kernel, cudaFuncAttributeMaxDynamicSharedMemorySize, smem_bytes);
    gru2_kernel<<<128, 256, smem_bytes>>>(x, wih0, whh0, bih0, bhh0,
                                          wih1, whh1, bih1, bhh1, wcls, bcls, out);
}